// round 10
// baseline (speedup 1.0000x reference)
#include <cuda_runtime.h>
#include <cuda_bf16.h>
#include <math.h>
#include <stdint.h>

// Fixed problem shape
#define BATCH 4
#define SEQ   2048
#define DMODEL 1024
#define NHEAD 16
#define HD    64
#define MM (BATCH*SEQ)     // 8192
#define KK DMODEL          // 1024
#define NN DMODEL          // 1024

// bf16 split operands (device globals; no allocation allowed)
__device__ __nv_bfloat16 g_Xhi[MM*KK];
__device__ __nv_bfloat16 g_Xlo[MM*KK];
__device__ __nv_bfloat16 g_Whi[4][NN*KK];   // transposed weights [N][K]
__device__ __nv_bfloat16 g_Wlo[4][NN*KK];
__device__ __nv_bfloat16 g_Qhi[MM*NN];      // [b*SEQ+n][h*64+d], pre-scaled 0.125
__device__ __nv_bfloat16 g_Qlo[MM*NN];
__device__ __nv_bfloat16 g_Khi[MM*NN];
__device__ __nv_bfloat16 g_Klo[MM*NN];
__device__ __nv_bfloat16 g_Vthi[MM*NN];     // [(b*16+h)*64+d][key]  (transposed)
__device__ __nv_bfloat16 g_Vtlo[MM*NN];
__device__ __nv_bfloat16 g_AOhi[MM*NN];
__device__ __nv_bfloat16 g_AOlo[MM*NN];

// ---------------------------------------------------------------------------
__device__ __forceinline__ uint32_t smem_u32(const void* p) {
    uint32_t a;
    asm("{ .reg .u64 t; cvta.to.shared.u64 t, %1; cvt.u32.u64 %0, t; }"
        : "=r"(a) : "l"(p));
    return a;
}
__device__ __forceinline__ void cp_async16(uint32_t dst, const void* src) {
    asm volatile("cp.async.cg.shared.global [%0], [%1], 16;"
                 :: "r"(dst), "l"(src) : "memory");
}
__device__ __forceinline__ void mma_bf16(float* d, const uint32_t* a,
                                         uint32_t b0, uint32_t b1) {
    asm volatile(
        "mma.sync.aligned.m16n8k16.row.col.f32.bf16.bf16.f32 "
        "{%0,%1,%2,%3}, {%4,%5,%6,%7}, {%8,%9}, {%0,%1,%2,%3};"
        : "+f"(d[0]), "+f"(d[1]), "+f"(d[2]), "+f"(d[3])
        : "r"(a[0]), "r"(a[1]), "r"(a[2]), "r"(a[3]), "r"(b0), "r"(b1));
}
__device__ __forceinline__ void split_bf16(float x, __nv_bfloat16& h, __nv_bfloat16& l) {
    h = __float2bfloat16_rn(x);
    l = __float2bfloat16_rn(x - __bfloat162float(h));
}
__device__ __forceinline__ void split_pack2(float f0, float f1,
                                            uint32_t& hp, uint32_t& lp) {
    __nv_bfloat16 h0, l0, h1, l1;
    split_bf16(f0, h0, l0);
    split_bf16(f1, h1, l1);
    hp = ((uint32_t)*(uint16_t*)&h1 << 16) | *(uint16_t*)&h0;
    lp = ((uint32_t)*(uint16_t*)&l1 << 16) | *(uint16_t*)&l0;
}

// ---------------------------------------------------------------------------
// Convert fp32 -> bf16 hi/lo (grid-stride, float4)
// ---------------------------------------------------------------------------
__global__ __launch_bounds__(256) void convert_split(
    const float* __restrict__ src, __nv_bfloat16* __restrict__ hi,
    __nv_bfloat16* __restrict__ lo, int n4)
{
    int idx = blockIdx.x * blockDim.x + threadIdx.x;
    int stride = gridDim.x * blockDim.x;
    for (int i = idx; i < n4; i += stride) {
        float4 v = ((const float4*)src)[i];
        __nv_bfloat16 h[4], l[4];
        split_bf16(v.x, h[0], l[0]);
        split_bf16(v.y, h[1], l[1]);
        split_bf16(v.z, h[2], l[2]);
        split_bf16(v.w, h[3], l[3]);
        ((uint2*)hi)[i] = *(uint2*)h;
        ((uint2*)lo)[i] = *(uint2*)l;
    }
}

// ---------------------------------------------------------------------------
// Transpose + split 4 weights: W[K][N] fp32 -> WT hi/lo [N][K] bf16
// ---------------------------------------------------------------------------
__global__ __launch_bounds__(256) void transpose_split4(
    const float* __restrict__ s0, const float* __restrict__ s1,
    const float* __restrict__ s2, const float* __restrict__ s3)
{
    const float* s;
    __nv_bfloat16 *dh, *dl;
    switch (blockIdx.z) {
        case 0: s = s0; dh = g_Whi[0]; dl = g_Wlo[0]; break;
        case 1: s = s1; dh = g_Whi[1]; dl = g_Wlo[1]; break;
        case 2: s = s2; dh = g_Whi[2]; dl = g_Wlo[2]; break;
        default: s = s3; dh = g_Whi[3]; dl = g_Wlo[3]; break;
    }
    __shared__ float t[32][33];
    int x0 = blockIdx.x * 32, y0 = blockIdx.y * 32;
    int tx = threadIdx.x, ty = threadIdx.y;
#pragma unroll
    for (int j = 0; j < 4; j++)
        t[ty + j * 8][tx] = s[(size_t)(y0 + ty + j * 8) * NN + x0 + tx];
    __syncthreads();
#pragma unroll
    for (int j = 0; j < 4; j++) {
        float v = t[tx][ty + j * 8];
        __nv_bfloat16 h, l;
        split_bf16(v, h, l);
        size_t o = (size_t)(x0 + ty + j * 8) * KK + y0 + tx;
        dh[o] = h;
        dl[o] = l;
    }
}

// ---------------------------------------------------------------------------
// bf16-split GEMM via mma.sync. BK=32, 2-stage cp.async, 2 CTAs/SM.
// ROWB=80: 16B-aligned rows (cp.async requirement), 20-word stride -> no
// bank conflicts (lr*20+lq mod 32 is a permutation of 0..31).
// MODE: 0 = fp32 out + bias; 1 = bf16 hi/lo out scaled; 2 = bf16 transposed V.
// ---------------------------------------------------------------------------
#define BKC 32
#define NCHUNKS (KK / BKC)            // 32
#define ROWB 80                       // 64B data + 16B pad (16B aligned!)
#define ARR_BYTES (128 * ROWB)        // 10240
#define STAGE_BYTES (4 * ARR_BYTES)   // 40960
#define NSTAGE 2
#define GEMM_SMEM (NSTAGE * STAGE_BYTES)  // 81920 -> 2 CTAs/SM

template <int MODE>
__global__ __launch_bounds__(256, 2) void gemm_bf16(
    const __nv_bfloat16* __restrict__ Ahi, const __nv_bfloat16* __restrict__ Alo,
    const __nv_bfloat16* __restrict__ Bhi, const __nv_bfloat16* __restrict__ Blo,
    float* __restrict__ C, const float* __restrict__ bias,
    __nv_bfloat16* __restrict__ Ohi, __nv_bfloat16* __restrict__ Olo,
    float scale)
{
    extern __shared__ __align__(16) char smb[];
    const uint32_t sbase = smem_u32(smb);
    const int tid = threadIdx.x;
    const int wid = tid >> 5;
    const int l = tid & 31;
    const int wm = wid & 3;
    const int wn = wid >> 2;
    const int m0 = blockIdx.y * 128;
    const int n0 = blockIdx.x * 128;

    float acc[2][8][4];
#pragma unroll
    for (int f = 0; f < 2; f++)
#pragma unroll
        for (int g = 0; g < 8; g++)
#pragma unroll
            for (int r = 0; r < 4; r++) acc[f][g][r] = 0.0f;

    // cp.async issue of chunk c into stage c&1: 4 arrays x 128 rows x 64B
    auto issue = [&](int c) {
        const int kc0 = c * BKC;
        const uint32_t sb = sbase + (c & 1) * STAGE_BYTES;
#pragma unroll
        for (int i = 0; i < 8; i++) {
            int id = tid + i * 256;        // 0..2047
            int arr = id >> 9;             // 0..3
            int rc = id & 511;
            int row = rc >> 2;             // 0..127
            int ch = rc & 3;               // 16B chunk in 64B row
            const __nv_bfloat16* gp;
            int grow;
            if (arr == 0)      { gp = Ahi; grow = m0 + row; }
            else if (arr == 1) { gp = Alo; grow = m0 + row; }
            else if (arr == 2) { gp = Bhi; grow = n0 + row; }
            else               { gp = Blo; grow = n0 + row; }
            const void* src = gp + (size_t)grow * KK + kc0 + ch * 8;
            uint32_t dst = sb + arr * ARR_BYTES + row * ROWB + ch * 16;
            cp_async16(dst, src);
        }
    };

    issue(0);
    asm volatile("cp.async.commit_group;" ::: "memory");

    const int lr = l >> 2;
    const int lc = (l & 3) * 2;

    for (int c = 0; c < NCHUNKS; c++) {
        if (c + 1 < NCHUNKS) {
            issue(c + 1);
            asm volatile("cp.async.commit_group;" ::: "memory");
            asm volatile("cp.async.wait_group 1;" ::: "memory");
        } else {
            asm volatile("cp.async.wait_group 0;" ::: "memory");
        }
        __syncthreads();

        const char* sb = smb + (c & 1) * STAGE_BYTES;
#pragma unroll
        for (int ks = 0; ks < 2; ks++) {
            const int kc = ks * 16 + lc;
            uint32_t ahi[2][4], alo[2][4];
#pragma unroll
            for (int f = 0; f < 2; f++) {
                int rowA = wm * 32 + f * 16 + lr;
                const char* pa = sb + rowA * ROWB + kc * 2;
                ahi[f][0] = *(const uint32_t*)(pa);
                ahi[f][1] = *(const uint32_t*)(pa + 8 * ROWB);
                ahi[f][2] = *(const uint32_t*)(pa + 16);
                ahi[f][3] = *(const uint32_t*)(pa + 8 * ROWB + 16);
                const char* pl = pa + ARR_BYTES;
                alo[f][0] = *(const uint32_t*)(pl);
                alo[f][1] = *(const uint32_t*)(pl + 8 * ROWB);
                alo[f][2] = *(const uint32_t*)(pl + 16);
                alo[f][3] = *(const uint32_t*)(pl + 8 * ROWB + 16);
            }
            // n-groups in halves of 4 to bound live registers (<=128 for 2 CTAs/SM)
#pragma unroll
            for (int gh = 0; gh < 2; gh++) {
                uint32_t bh0[4], bh1[4], bl0[4], bl1[4];
#pragma unroll
                for (int gi = 0; gi < 4; gi++) {
                    int g = gh * 4 + gi;
                    int rowBn = wn * 64 + g * 8 + lr;
                    const char* pb = sb + 2 * ARR_BYTES + rowBn * ROWB + kc * 2;
                    bh0[gi] = *(const uint32_t*)(pb);
                    bh1[gi] = *(const uint32_t*)(pb + 16);
                    bl0[gi] = *(const uint32_t*)(pb + ARR_BYTES);
                    bl1[gi] = *(const uint32_t*)(pb + ARR_BYTES + 16);
                }
#pragma unroll
                for (int gi = 0; gi < 4; gi++)
#pragma unroll
                    for (int f = 0; f < 2; f++)
                        mma_bf16(acc[f][gh * 4 + gi], ahi[f], bh0[gi], bh1[gi]);
#pragma unroll
                for (int gi = 0; gi < 4; gi++)
#pragma unroll
                    for (int f = 0; f < 2; f++)
                        mma_bf16(acc[f][gh * 4 + gi], ahi[f], bl0[gi], bl1[gi]);
#pragma unroll
                for (int gi = 0; gi < 4; gi++)
#pragma unroll
                    for (int f = 0; f < 2; f++)
                        mma_bf16(acc[f][gh * 4 + gi], alo[f], bh0[gi], bh1[gi]);
            }
        }
        __syncthreads();
    }

    // Epilogue
#pragma unroll
    for (int f = 0; f < 2; f++) {
        int r0 = m0 + wm * 32 + f * 16 + lr;
#pragma unroll
        for (int g = 0; g < 8; g++) {
            int cc = n0 + wn * 64 + g * 8 + lc;
            if (MODE == 0) {
                float bx = bias[cc], by = bias[cc + 1];
                float2 v0 = make_float2(acc[f][g][0] + bx, acc[f][g][1] + by);
                float2 v1 = make_float2(acc[f][g][2] + bx, acc[f][g][3] + by);
                *(float2*)(C + (size_t)r0 * NN + cc) = v0;
                *(float2*)(C + (size_t)(r0 + 8) * NN + cc) = v1;
            } else if (MODE == 1) {
                uint32_t hp, lp;
                split_pack2(acc[f][g][0] * scale, acc[f][g][1] * scale, hp, lp);
                *(uint32_t*)(Ohi + (size_t)r0 * NN + cc) = hp;
                *(uint32_t*)(Olo + (size_t)r0 * NN + cc) = lp;
                split_pack2(acc[f][g][2] * scale, acc[f][g][3] * scale, hp, lp);
                *(uint32_t*)(Ohi + (size_t)(r0 + 8) * NN + cc) = hp;
                *(uint32_t*)(Olo + (size_t)(r0 + 8) * NN + cc) = lp;
            } else {
#pragma unroll
                for (int rr = 0; rr < 2; rr++) {
                    int row = r0 + rr * 8;
                    int b = row >> 11, n = row & 2047;
#pragma unroll
                    for (int cj = 0; cj < 2; cj++) {
                        int col = cc + cj;
                        float v = acc[f][g][rr * 2 + cj];
                        __nv_bfloat16 h, lo2;
                        split_bf16(v, h, lo2);
                        size_t o = ((size_t)(b * 16) * 64 + col) * SEQ + n;
                        Ohi[o] = h;
                        Olo[o] = lo2;
                    }
                }
            }
        }
    }
}

// ---------------------------------------------------------------------------
// Tensor-core flash attention (causal), bf16 3-term split. (unchanged R5/R6)
// ---------------------------------------------------------------------------
#define FQ_HI 0
#define FQ_LO 9216
#define FK_BASE 18432
#define FV_BASE 55296
#define FP_HI 92160
#define FP_LO 101376
#define FLASH_SMEM 110592

__global__ __launch_bounds__(128, 2) void flash_tc(
    const __nv_bfloat16* __restrict__ Qhi, const __nv_bfloat16* __restrict__ Qlo,
    const __nv_bfloat16* __restrict__ Khi, const __nv_bfloat16* __restrict__ Klo,
    const __nv_bfloat16* __restrict__ Vthi, const __nv_bfloat16* __restrict__ Vtlo,
    __nv_bfloat16* __restrict__ AOhi, __nv_bfloat16* __restrict__ AOlo)
{
    extern __shared__ __align__(16) char smf[];
    const uint32_t sb = smem_u32(smf);
    const int tid = threadIdx.x;
    const int w = tid >> 5;
    const int l = tid & 31;
    const int lr = l >> 2;
    const int lq = l & 3;
    const int ib = gridDim.x - 1 - blockIdx.x;
    const int bh = blockIdx.y;
    const int b = bh >> 4;
    const int h = bh & 15;
    const int i0 = ib * 64;
    const size_t qrow0 = (size_t)b * SEQ + i0;

#pragma unroll
    for (int i = 0; i < 8; i++) {
        int id = tid + i * 128;
        int arr = id >> 9;
        int rc = id & 511;
        int row = rc >> 3, ch = rc & 7;
        const __nv_bfloat16* gp = arr ? Qlo : Qhi;
        cp_async16(sb + arr * 9216 + row * 144 + ch * 16,
                   gp + (qrow0 + row) * DMODEL + h * 64 + ch * 8);
    }

    auto issueKV = [&](int jb) {
        const int s = jb & 1;
        const int j0 = jb * 64;
#pragma unroll
        for (int i = 0; i < 16; i++) {
            int id = tid + i * 128;
            int half = id >> 10;
            int rc = id & 1023;
            int arr = rc >> 9;
            int r2 = rc & 511;
            int row = r2 >> 3, ch = r2 & 7;
            const __nv_bfloat16* gp;
            const void* src;
            uint32_t dst;
            if (half == 0) {
                gp = arr ? Klo : Khi;
                src = gp + ((size_t)b * SEQ + j0 + row) * DMODEL + h * 64 + ch * 8;
                dst = sb + FK_BASE + s * 18432 + arr * 9216 + row * 144 + ch * 16;
            } else {
                gp = arr ? Vtlo : Vthi;
                src = gp + ((size_t)bh * 64 + row) * SEQ + j0 + ch * 8;
                dst = sb + FV_BASE + s * 18432 + arr * 9216 + row * 144 + ch * 16;
            }
            cp_async16(dst, src);
        }
    };

    issueKV(0);
    asm volatile("cp.async.commit_group;" ::: "memory");

    float mrow[2] = {-1e30f, -1e30f};
    float lsum[2] = {0.0f, 0.0f};
    float oacc[8][4];
#pragma unroll
    for (int g = 0; g < 8; g++)
#pragma unroll
        for (int r = 0; r < 4; r++) oacc[g][r] = 0.0f;

    for (int jb = 0; jb <= ib; jb++) {
        const int s = jb & 1;
        if (jb < ib) {
            issueKV(jb + 1);
            asm volatile("cp.async.commit_group;" ::: "memory");
            asm volatile("cp.async.wait_group 1;" ::: "memory");
        } else {
            asm volatile("cp.async.wait_group 0;" ::: "memory");
        }
        __syncthreads();

        float sacc[8][4];
#pragma unroll
        for (int g = 0; g < 8; g++)
#pragma unroll
            for (int r = 0; r < 4; r++) sacc[g][r] = 0.0f;

        const char* qh = smf;
        const char* kb = smf + FK_BASE + s * 18432;
#pragma unroll
        for (int ks = 0; ks < 4; ks++) {
            const int kc = ks * 32 + lq * 4;
            uint32_t ahi[4], alo[4];
            {
                const char* pa = qh + (w * 16 + lr) * 144 + kc;
                ahi[0] = *(const uint32_t*)(pa);
                ahi[1] = *(const uint32_t*)(pa + 8 * 144);
                ahi[2] = *(const uint32_t*)(pa + 16);
                ahi[3] = *(const uint32_t*)(pa + 8 * 144 + 16);
                const char* pl = pa + 9216;
                alo[0] = *(const uint32_t*)(pl);
                alo[1] = *(const uint32_t*)(pl + 8 * 144);
                alo[2] = *(const uint32_t*)(pl + 16);
                alo[3] = *(const uint32_t*)(pl + 8 * 144 + 16);
            }
            uint32_t bh0[8], bh1[8], bl0[8], bl1[8];
#pragma unroll
            for (int g = 0; g < 8; g++) {
                const char* pb = kb + (g * 8 + lr) * 144 + kc;
                bh0[g] = *(const uint32_t*)(pb);
                bh1[g] = *(const uint32_t*)(pb + 16);
                bl0[g] = *(const uint32_t*)(pb + 9216);
                bl1[g] = *(const uint32_t*)(pb + 9216 + 16);
            }
#pragma unroll
            for (int g = 0; g < 8; g++) mma_bf16(sacc[g], ahi, bh0[g], bh1[g]);
#pragma unroll
            for (int g = 0; g < 8; g++) mma_bf16(sacc[g], ahi, bl0[g], bl1[g]);
#pragma unroll
            for (int g = 0; g < 8; g++) mma_bf16(sacc[g], alo, bh0[g], bh1[g]);
        }

        if (jb == ib) {
#pragma unroll
            for (int g = 0; g < 8; g++)
#pragma unroll
                for (int r = 0; r < 4; r++) {
                    int rowL = w * 16 + lr + (r >> 1) * 8;
                    int colL = g * 8 + lq * 2 + (r & 1);
                    if (colL > rowL) sacc[g][r] = -1e30f;
                }
        }

#pragma unroll
        for (int ri = 0; ri < 2; ri++) {
            const int c0 = ri * 2;
            float rmax = -1e30f;
#pragma unroll
            for (int g = 0; g < 8; g++)
                rmax = fmaxf(rmax, fmaxf(sacc[g][c0], sacc[g][c0 + 1]));
            rmax = fmaxf(rmax, __shfl_xor_sync(0xffffffffu, rmax, 1));
            rmax = fmaxf(rmax, __shfl_xor_sync(0xffffffffu, rmax, 2));
            float mnew = fmaxf(mrow[ri], rmax);
            float alpha = __expf(mrow[ri] - mnew);
            float rsum = 0.0f;
            const int prow = w * 16 + lr + ri * 8;
#pragma unroll
            for (int g = 0; g < 8; g++) {
                float p0 = __expf(sacc[g][c0] - mnew);
                float p1 = __expf(sacc[g][c0 + 1] - mnew);
                rsum += p0 + p1;
                uint32_t hp, lp;
                split_pack2(p0, p1, hp, lp);
                int boff = prow * 144 + (g * 8 + lq * 2) * 2;
                *(uint32_t*)(smf + FP_HI + boff) = hp;
                *(uint32_t*)(smf + FP_LO + boff) = lp;
            }
            rsum += __shfl_xor_sync(0xffffffffu, rsum, 1);
            rsum += __shfl_xor_sync(0xffffffffu, rsum, 2);
            lsum[ri] = lsum[ri] * alpha + rsum;
            mrow[ri] = mnew;
#pragma unroll
            for (int g = 0; g < 8; g++) {
                oacc[g][c0] *= alpha;
                oacc[g][c0 + 1] *= alpha;
            }
        }
        __syncwarp();

        const char* vb = smf + FV_BASE + s * 18432;
#pragma unroll
        for (int ks = 0; ks < 4; ks++) {
            const int kc = ks * 32 + lq * 4;
            uint32_t phi[4], plo[4];
            {
                const char* pa = smf + FP_HI + (w * 16 + lr) * 144 + kc;
                phi[0] = *(const uint32_t*)(pa);
                phi[1] = *(const uint32_t*)(pa + 8 * 144);
                phi[2] = *(const uint32_t*)(pa + 16);
                phi[3] = *(const uint32_t*)(pa + 8 * 144 + 16);
                const char* pl = smf + FP_LO + (w * 16 + lr) * 144 + kc;
                plo[0] = *(const uint32_t*)(pl);
                plo[1] = *(const uint32_t*)(pl + 8 * 144);
                plo[2] = *(const uint32_t*)(pl + 16);
                plo[3] = *(const uint32_t*)(pl + 8 * 144 + 16);
            }
            uint32_t bh0[8], bh1[8], bl0[8], bl1[8];
#pragma unroll
            for (int g = 0; g < 8; g++) {
                const char* pb = vb + (g * 8 + lr) * 144 + kc;
                bh0[g] = *(const uint32_t*)(pb);
                bh1[g] = *(const uint32_t*)(pb + 16);
                bl0[g] = *(const uint32_t*)(pb + 9216);
                bl1[g] = *(const uint32_t*)(pb + 9216 + 16);
            }
#pragma unroll
            for (int g = 0; g < 8; g++) mma_bf16(oacc[g], phi, bh0[g], bh1[g]);
#pragma unroll
            for (int g = 0; g < 8; g++) mma_bf16(oacc[g], phi, bl0[g], bl1[g]);
#pragma unroll
            for (int g = 0; g < 8; g++) mma_bf16(oacc[g], plo, bh0[g], bh1[g]);
        }
        __syncthreads();
    }

#pragma unroll
    for (int ri = 0; ri < 2; ri++) {
        float inv = 1.0f / lsum[ri];
        size_t grow = qrow0 + w * 16 + lr + ri * 8;
#pragma unroll
        for (int g = 0; g < 8; g++) {
            int col = h * 64 + g * 8 + lq * 2;
            uint32_t hp, lp;
            split_pack2(oacc[g][ri * 2] * inv, oacc[g][ri * 2 + 1] * inv, hp, lp);
            *(uint32_t*)(AOhi + grow * DMODEL + col) = hp;
            *(uint32_t*)(AOlo + grow * DMODEL + col) = lp;
        }
    }
}

// ---------------------------------------------------------------------------
extern "C" void kernel_launch(void* const* d_in, const int* in_sizes, int n_in,
                              void* d_out, int out_size)
{
    (void)in_sizes; (void)n_in; (void)out_size;
    const float* x  = (const float*)d_in[0];
    const float* Wq = (const float*)d_in[1];
    const float* Wk = (const float*)d_in[2];
    const float* Wv = (const float*)d_in[3];
    const float* Wo = (const float*)d_in[4];
    const float* bo = (const float*)d_in[5];
    float* out = (float*)d_out;

    __nv_bfloat16 *Xhi, *Xlo, *Whi, *Wlo, *Qhi, *Qlo, *Khi, *Klo,
                  *Vthi, *Vtlo, *AOhi, *AOlo;
    cudaGetSymbolAddress((void**)&Xhi,  g_Xhi);
    cudaGetSymbolAddress((void**)&Xlo,  g_Xlo);
    cudaGetSymbolAddress((void**)&Whi,  g_Whi);
    cudaGetSymbolAddress((void**)&Wlo,  g_Wlo);
    cudaGetSymbolAddress((void**)&Qhi,  g_Qhi);
    cudaGetSymbolAddress((void**)&Qlo,  g_Qlo);
    cudaGetSymbolAddress((void**)&Khi,  g_Khi);
    cudaGetSymbolAddress((void**)&Klo,  g_Klo);
    cudaGetSymbolAddress((void**)&Vthi, g_Vthi);
    cudaGetSymbolAddress((void**)&Vtlo, g_Vtlo);
    cudaGetSymbolAddress((void**)&AOhi, g_AOhi);
    cudaGetSymbolAddress((void**)&AOlo, g_AOlo);

    convert_split<<<512, 256>>>(x, Xhi, Xlo, MM * KK / 4);
    transpose_split4<<<dim3(32, 32, 4), dim3(32, 8)>>>(Wq, Wk, Wv, Wo);

    cudaFuncSetAttribute(gemm_bf16<0>, cudaFuncAttributeMaxDynamicSharedMemorySize, GEMM_SMEM);
    cudaFuncSetAttribute(gemm_bf16<1>, cudaFuncAttributeMaxDynamicSharedMemorySize, GEMM_SMEM);
    cudaFuncSetAttribute(gemm_bf16<2>, cudaFuncAttributeMaxDynamicSharedMemorySize, GEMM_SMEM);
    dim3 gg(NN / 128, MM / 128);
    gemm_bf16<1><<<gg, 256, GEMM_SMEM>>>(Xhi, Xlo, Whi + 0 * (size_t)NN * KK,
                                         Wlo + 0 * (size_t)NN * KK,
                                         nullptr, nullptr, Qhi, Qlo, 0.125f);
    gemm_bf16<1><<<gg, 256, GEMM_SMEM>>>(Xhi, Xlo, Whi + 1 * (size_t)NN * KK,
                                         Wlo + 1 * (size_t)NN * KK,
                                         nullptr, nullptr, Khi, Klo, 1.0f);
    gemm_bf16<2><<<gg, 256, GEMM_SMEM>>>(Xhi, Xlo, Whi + 2 * (size_t)NN * KK,
                                         Wlo + 2 * (size_t)NN * KK,
                                         nullptr, nullptr, Vthi, Vtlo, 1.0f);

    cudaFuncSetAttribute(flash_tc, cudaFuncAttributeMaxDynamicSharedMemorySize, FLASH_SMEM);
    flash_tc<<<dim3(SEQ / 64, BATCH * NHEAD), 128, FLASH_SMEM>>>(
        Qhi, Qlo, Khi, Klo, Vthi, Vtlo, AOhi, AOlo);

    gemm_bf16<0><<<gg, 256, GEMM_SMEM>>>(AOhi, AOlo, Whi + 3 * (size_t)NN * KK,
                                         Wlo + 3 * (size_t)NN * KK,
                                         out, bo, nullptr, nullptr, 1.0f);
}

// round 13
// speedup vs baseline: 1.4186x; 1.4186x over previous
#include <cuda_runtime.h>
#include <cuda_fp16.h>
#include <math.h>
#include <stdint.h>

// Fixed problem shape
#define BATCH 4
#define SEQ   2048
#define DMODEL 1024
#define NHEAD 16
#define HD    64
#define MM (BATCH*SEQ)     // 8192
#define KK DMODEL          // 1024
#define NN DMODEL          // 1024

// fp16 operands (device globals; no allocation allowed)
__device__ __half g_Xhi[MM*KK];
__device__ __half g_Xlo[MM*KK];
__device__ __half g_W[4][NN*KK];       // transposed weights [N][K], single fp16
__device__ __half g_Qhi[MM*NN];        // pre-scaled 0.125, hi/lo pair
__device__ __half g_Qlo[MM*NN];
__device__ __half g_Ks[MM*NN];         // K single fp16
__device__ __half g_Vt[MM*NN];         // V transposed [(b*16+h)*64+d][key], single
__device__ __half g_AOhi[MM*NN];
__device__ __half g_AOlo[MM*NN];

// ---------------------------------------------------------------------------
__device__ __forceinline__ uint32_t smem_u32(const void* p) {
    uint32_t a;
    asm("{ .reg .u64 t; cvta.to.shared.u64 t, %1; cvt.u32.u64 %0, t; }"
        : "=r"(a) : "l"(p));
    return a;
}
__device__ __forceinline__ void cp_async16(uint32_t dst, const void* src) {
    asm volatile("cp.async.cg.shared.global [%0], [%1], 16;"
                 :: "r"(dst), "l"(src) : "memory");
}
__device__ __forceinline__ void mma_f16(float* d, const uint32_t* a,
                                        uint32_t b0, uint32_t b1) {
    asm volatile(
        "mma.sync.aligned.m16n8k16.row.col.f32.f16.f16.f32 "
        "{%0,%1,%2,%3}, {%4,%5,%6,%7}, {%8,%9}, {%0,%1,%2,%3};"
        : "+f"(d[0]), "+f"(d[1]), "+f"(d[2]), "+f"(d[3])
        : "r"(a[0]), "r"(a[1]), "r"(a[2]), "r"(a[3]), "r"(b0), "r"(b1));
}
__device__ __forceinline__ void split_h(float x, __half& h, __half& l) {
    h = __float2half_rn(x);
    l = __float2half_rn(x - __half2float(h));
}
__device__ __forceinline__ uint16_t h_bits(__half h) { return *(uint16_t*)&h; }
__device__ __forceinline__ uint32_t pack2h(float f0, float f1) {
    __half h0 = __float2half_rn(f0), h1 = __float2half_rn(f1);
    return ((uint32_t)h_bits(h1) << 16) | h_bits(h0);
}
__device__ __forceinline__ void split_pack2h(float f0, float f1,
                                             uint32_t& hp, uint32_t& lp) {
    __half h0, l0, h1, l1;
    split_h(f0, h0, l0);
    split_h(f1, h1, l1);
    hp = ((uint32_t)h_bits(h1) << 16) | h_bits(h0);
    lp = ((uint32_t)h_bits(l1) << 16) | h_bits(l0);
}

// ---------------------------------------------------------------------------
// Convert fp32 -> fp16 hi/lo (grid-stride, float4)
// ---------------------------------------------------------------------------
__global__ __launch_bounds__(256) void convert_split_h(
    const float* __restrict__ src, __half* __restrict__ hi,
    __half* __restrict__ lo, int n4)
{
    int idx = blockIdx.x * blockDim.x + threadIdx.x;
    int stride = gridDim.x * blockDim.x;
    for (int i = idx; i < n4; i += stride) {
        float4 v = ((const float4*)src)[i];
        __half h[4], l[4];
        split_h(v.x, h[0], l[0]);
        split_h(v.y, h[1], l[1]);
        split_h(v.z, h[2], l[2]);
        split_h(v.w, h[3], l[3]);
        ((uint2*)hi)[i] = *(uint2*)h;
        ((uint2*)lo)[i] = *(uint2*)l;
    }
}

// ---------------------------------------------------------------------------
// Transpose 4 weights: W[K][N] fp32 -> WT [N][K] single fp16
// ---------------------------------------------------------------------------
__global__ __launch_bounds__(256) void transpose_half4(
    const float* __restrict__ s0, const float* __restrict__ s1,
    const float* __restrict__ s2, const float* __restrict__ s3)
{
    const float* s;
    __half* d;
    switch (blockIdx.z) {
        case 0: s = s0; d = g_W[0]; break;
        case 1: s = s1; d = g_W[1]; break;
        case 2: s = s2; d = g_W[2]; break;
        default: s = s3; d = g_W[3]; break;
    }
    __shared__ float t[32][33];
    int x0 = blockIdx.x * 32, y0 = blockIdx.y * 32;
    int tx = threadIdx.x, ty = threadIdx.y;
#pragma unroll
    for (int j = 0; j < 4; j++)
        t[ty + j * 8][tx] = s[(size_t)(y0 + ty + j * 8) * NN + x0 + tx];
    __syncthreads();
#pragma unroll
    for (int j = 0; j < 4; j++)
        d[(size_t)(x0 + ty + j * 8) * KK + y0 + tx] = __float2half_rn(t[tx][ty + j * 8]);
}

// ---------------------------------------------------------------------------
// fp16 asymmetric-split GEMM: C = (Ahi+Alo)[M,K] @ B[N,K]^T, 2 MMAs/product.
// BK=32, 2-stage cp.async, 2 CTAs/SM. ROWB=80 (16B-aligned, conflict-free).
// MODE: 0 = fp32 out + bias; 1 = fp16 hi/lo out scaled (Q);
//       2 = fp16 single out natural (K); 3 = fp16 single transposed (V).
// ---------------------------------------------------------------------------
#define BKC 32
#define NCHUNKS (KK / BKC)            // 32
#define ROWB 80
#define ARR_BYTES (128 * ROWB)        // 10240
#define STAGE_BYTES (3 * ARR_BYTES)   // Ahi, Alo, B = 30720
#define GEMM_SMEM (2 * STAGE_BYTES)   // 61440 -> 2 CTAs/SM

template <int MODE>
__global__ __launch_bounds__(256, 2) void gemm_h(
    const __half* __restrict__ Ahi, const __half* __restrict__ Alo,
    const __half* __restrict__ B,
    float* __restrict__ C, const float* __restrict__ bias,
    __half* __restrict__ Ohi, __half* __restrict__ Olo,
    __half* __restrict__ Osng, float scale)
{
    extern __shared__ __align__(16) char smb[];
    const uint32_t sbase = smem_u32(smb);
    const int tid = threadIdx.x;
    const int wid = tid >> 5;
    const int l = tid & 31;
    const int wm = wid & 3;
    const int wn = wid >> 2;
    const int m0 = blockIdx.y * 128;
    const int n0 = blockIdx.x * 128;

    float acc[2][8][4];
#pragma unroll
    for (int f = 0; f < 2; f++)
#pragma unroll
        for (int g = 0; g < 8; g++)
#pragma unroll
            for (int r = 0; r < 4; r++) acc[f][g][r] = 0.0f;

    // cp.async chunk c -> stage c&1: 3 arrays x 128 rows x 64B = 1536 chunks
    auto issue = [&](int c) {
        const int kc0 = c * BKC;
        const uint32_t sb = sbase + (c & 1) * STAGE_BYTES;
#pragma unroll
        for (int i = 0; i < 6; i++) {
            int id = tid + i * 256;        // 0..1535
            int arr = id >> 9;             // 0..2
            int rc = id & 511;
            int row = rc >> 2;
            int ch = rc & 3;
            const __half* gp;
            int grow;
            if (arr == 0)      { gp = Ahi; grow = m0 + row; }
            else if (arr == 1) { gp = Alo; grow = m0 + row; }
            else               { gp = B;   grow = n0 + row; }
            const void* src = gp + (size_t)grow * KK + kc0 + ch * 8;
            uint32_t dst = sb + arr * ARR_BYTES + row * ROWB + ch * 16;
            cp_async16(dst, src);
        }
    };

    issue(0);
    asm volatile("cp.async.commit_group;" ::: "memory");

    const int lr = l >> 2;
    const int lc = (l & 3) * 2;

    for (int c = 0; c < NCHUNKS; c++) {
        if (c + 1 < NCHUNKS) {
            issue(c + 1);
            asm volatile("cp.async.commit_group;" ::: "memory");
            asm volatile("cp.async.wait_group 1;" ::: "memory");
        } else {
            asm volatile("cp.async.wait_group 0;" ::: "memory");
        }
        __syncthreads();

        const char* sb = smb + (c & 1) * STAGE_BYTES;
#pragma unroll
        for (int ks = 0; ks < 2; ks++) {
            const int kc = ks * 16 + lc;
            uint32_t ahi[2][4], alo[2][4];
#pragma unroll
            for (int f = 0; f < 2; f++) {
                int rowA = wm * 32 + f * 16 + lr;
                const char* pa = sb + rowA * ROWB + kc * 2;
                ahi[f][0] = *(const uint32_t*)(pa);
                ahi[f][1] = *(const uint32_t*)(pa + 8 * ROWB);
                ahi[f][2] = *(const uint32_t*)(pa + 16);
                ahi[f][3] = *(const uint32_t*)(pa + 8 * ROWB + 16);
                const char* pl = pa + ARR_BYTES;
                alo[f][0] = *(const uint32_t*)(pl);
                alo[f][1] = *(const uint32_t*)(pl + 8 * ROWB);
                alo[f][2] = *(const uint32_t*)(pl + 16);
                alo[f][3] = *(const uint32_t*)(pl + 8 * ROWB + 16);
            }
            uint32_t b0[8], b1[8];
#pragma unroll
            for (int g = 0; g < 8; g++) {
                int rowBn = wn * 64 + g * 8 + lr;
                const char* pb = sb + 2 * ARR_BYTES + rowBn * ROWB + kc * 2;
                b0[g] = *(const uint32_t*)(pb);
                b1[g] = *(const uint32_t*)(pb + 16);
            }
#pragma unroll
            for (int g = 0; g < 8; g++)
#pragma unroll
                for (int f = 0; f < 2; f++)
                    mma_f16(acc[f][g], ahi[f], b0[g], b1[g]);
#pragma unroll
            for (int g = 0; g < 8; g++)
#pragma unroll
                for (int f = 0; f < 2; f++)
                    mma_f16(acc[f][g], alo[f], b0[g], b1[g]);
        }
        __syncthreads();
    }

    // Epilogue
#pragma unroll
    for (int f = 0; f < 2; f++) {
        int r0 = m0 + wm * 32 + f * 16 + lr;
#pragma unroll
        for (int g = 0; g < 8; g++) {
            int cc = n0 + wn * 64 + g * 8 + lc;
            if (MODE == 0) {
                float bx = bias[cc], by = bias[cc + 1];
                float2 v0 = make_float2(acc[f][g][0] + bx, acc[f][g][1] + by);
                float2 v1 = make_float2(acc[f][g][2] + bx, acc[f][g][3] + by);
                *(float2*)(C + (size_t)r0 * NN + cc) = v0;
                *(float2*)(C + (size_t)(r0 + 8) * NN + cc) = v1;
            } else if (MODE == 1) {
                uint32_t hp, lp;
                split_pack2h(acc[f][g][0] * scale, acc[f][g][1] * scale, hp, lp);
                *(uint32_t*)(Ohi + (size_t)r0 * NN + cc) = hp;
                *(uint32_t*)(Olo + (size_t)r0 * NN + cc) = lp;
                split_pack2h(acc[f][g][2] * scale, acc[f][g][3] * scale, hp, lp);
                *(uint32_t*)(Ohi + (size_t)(r0 + 8) * NN + cc) = hp;
                *(uint32_t*)(Olo + (size_t)(r0 + 8) * NN + cc) = lp;
            } else if (MODE == 2) {
                *(uint32_t*)(Osng + (size_t)r0 * NN + cc) =
                    pack2h(acc[f][g][0], acc[f][g][1]);
                *(uint32_t*)(Osng + (size_t)(r0 + 8) * NN + cc) =
                    pack2h(acc[f][g][2], acc[f][g][3]);
            } else {
#pragma unroll
                for (int rr = 0; rr < 2; rr++) {
                    int row = r0 + rr * 8;
                    int b = row >> 11, n = row & 2047;
#pragma unroll
                    for (int cj = 0; cj < 2; cj++) {
                        int col = cc + cj;          // = h*64 + d
                        size_t o = ((size_t)(b * 16) * 64 + col) * SEQ + n;
                        Osng[o] = __float2half_rn(acc[f][g][rr * 2 + cj]);
                    }
                }
            }
        }
    }
}

// ---------------------------------------------------------------------------
// Flash attention (causal), fp16 asymmetric split: Q/P hi-lo pairs (A side),
// K/Vt single fp16 (B side). 2 MMAs per product. BM=BN=64, 128 threads.
// smem: QH 0, QL 9216, K[s] 18432+s*9216, V[s] 36864+s*9216, PH 55296, PL 64512
// ---------------------------------------------------------------------------
#define FK_BASE 18432
#define FV_BASE 36864
#define FP_HI 55296
#define FP_LO 64512
#define FLASH_SMEM 73728

__global__ __launch_bounds__(128, 2) void flash_h(
    const __half* __restrict__ Qhi, const __half* __restrict__ Qlo,
    const __half* __restrict__ Ks,  const __half* __restrict__ Vt,
    __half* __restrict__ AOhi, __half* __restrict__ AOlo)
{
    extern __shared__ __align__(16) char smf[];
    const uint32_t sb = smem_u32(smf);
    const int tid = threadIdx.x;
    const int w = tid >> 5;
    const int l = tid & 31;
    const int lr = l >> 2;
    const int lq = l & 3;
    const int ib = gridDim.x - 1 - blockIdx.x;
    const int bh = blockIdx.y;
    const int b = bh >> 4;
    const int h = bh & 15;
    const int i0 = ib * 64;
    const size_t qrow0 = (size_t)b * SEQ + i0;

    // ---- load Q hi/lo: 2 arrays x 512 16B-chunks ----
#pragma unroll
    for (int i = 0; i < 8; i++) {
        int id = tid + i * 128;
        int arr = id >> 9;
        int rc = id & 511;
        int row = rc >> 3, ch = rc & 7;
        const __half* gp = arr ? Qlo : Qhi;
        cp_async16(sb + arr * 9216 + row * 144 + ch * 16,
                   gp + (qrow0 + row) * DMODEL + h * 64 + ch * 8);
    }

    auto issueKV = [&](int jb) {
        const int s = jb & 1;
        const int j0 = jb * 64;
#pragma unroll
        for (int i = 0; i < 8; i++) {
            int id = tid + i * 128;
            int seg = id >> 9;             // 0=K, 1=Vt
            int rc = id & 511;
            int row = rc >> 3, ch = rc & 7;
            const void* src;
            uint32_t dst;
            if (seg == 0) {
                src = Ks + ((size_t)b * SEQ + j0 + row) * DMODEL + h * 64 + ch * 8;
                dst = sb + FK_BASE + s * 9216 + row * 144 + ch * 16;
            } else {
                src = Vt + ((size_t)bh * 64 + row) * SEQ + j0 + ch * 8;
                dst = sb + FV_BASE + s * 9216 + row * 144 + ch * 16;
            }
            cp_async16(dst, src);
        }
    };

    issueKV(0);
    asm volatile("cp.async.commit_group;" ::: "memory");

    float mrow[2] = {-1e30f, -1e30f};
    float lsum[2] = {0.0f, 0.0f};
    float oacc[8][4];
#pragma unroll
    for (int g = 0; g < 8; g++)
#pragma unroll
        for (int r = 0; r < 4; r++) oacc[g][r] = 0.0f;

    for (int jb = 0; jb <= ib; jb++) {
        const int s = jb & 1;
        if (jb < ib) {
            issueKV(jb + 1);
            asm volatile("cp.async.commit_group;" ::: "memory");
            asm volatile("cp.async.wait_group 1;" ::: "memory");
        } else {
            asm volatile("cp.async.wait_group 0;" ::: "memory");
        }
        __syncthreads();

        // ---- S = Q @ K^T (2-term) ----
        float sacc[8][4];
#pragma unroll
        for (int g = 0; g < 8; g++)
#pragma unroll
            for (int r = 0; r < 4; r++) sacc[g][r] = 0.0f;

        const char* kb = smf + FK_BASE + s * 9216;
#pragma unroll
        for (int ks = 0; ks < 4; ks++) {
            const int kc = ks * 32 + lq * 4;
            uint32_t ahi[4], alo[4];
            {
                const char* pa = smf + (w * 16 + lr) * 144 + kc;
                ahi[0] = *(const uint32_t*)(pa);
                ahi[1] = *(const uint32_t*)(pa + 8 * 144);
                ahi[2] = *(const uint32_t*)(pa + 16);
                ahi[3] = *(const uint32_t*)(pa + 8 * 144 + 16);
                const char* pl = pa + 9216;
                alo[0] = *(const uint32_t*)(pl);
                alo[1] = *(const uint32_t*)(pl + 8 * 144);
                alo[2] = *(const uint32_t*)(pl + 16);
                alo[3] = *(const uint32_t*)(pl + 8 * 144 + 16);
            }
            uint32_t b0[8], b1[8];
#pragma unroll
            for (int g = 0; g < 8; g++) {
                const char* pb = kb + (g * 8 + lr) * 144 + kc;
                b0[g] = *(const uint32_t*)(pb);
                b1[g] = *(const uint32_t*)(pb + 16);
            }
#pragma unroll
            for (int g = 0; g < 8; g++) mma_f16(sacc[g], ahi, b0[g], b1[g]);
#pragma unroll
            for (int g = 0; g < 8; g++) mma_f16(sacc[g], alo, b0[g], b1[g]);
        }

        // ---- causal mask on diagonal block ----
        if (jb == ib) {
#pragma unroll
            for (int g = 0; g < 8; g++)
#pragma unroll
                for (int r = 0; r < 4; r++) {
                    int rowL = w * 16 + lr + (r >> 1) * 8;
                    int colL = g * 8 + lq * 2 + (r & 1);
                    if (colL > rowL) sacc[g][r] = -1e30f;
                }
        }

        // ---- online softmax + P split to smem ----
#pragma unroll
        for (int ri = 0; ri < 2; ri++) {
            const int c0 = ri * 2;
            float rmax = -1e30f;
#pragma unroll
            for (int g = 0; g < 8; g++)
                rmax = fmaxf(rmax, fmaxf(sacc[g][c0], sacc[g][c0 + 1]));
            rmax = fmaxf(rmax, __shfl_xor_sync(0xffffffffu, rmax, 1));
            rmax = fmaxf(rmax, __shfl_xor_sync(0xffffffffu, rmax, 2));
            float mnew = fmaxf(mrow[ri], rmax);
            float alpha = __expf(mrow[ri] - mnew);
            float rsum = 0.0f;
            const int prow = w * 16 + lr + ri * 8;
#pragma unroll
            for (int g = 0; g < 8; g++) {
                float p0 = __expf(sacc[g][c0] - mnew);
                float p1 = __expf(sacc[g][c0 + 1] - mnew);
                rsum += p0 + p1;
                uint32_t hp, lp;
                split_pack2h(p0, p1, hp, lp);
                int boff = prow * 144 + (g * 8 + lq * 2) * 2;
                *(uint32_t*)(smf + FP_HI + boff) = hp;
                *(uint32_t*)(smf + FP_LO + boff) = lp;
            }
            rsum += __shfl_xor_sync(0xffffffffu, rsum, 1);
            rsum += __shfl_xor_sync(0xffffffffu, rsum, 2);
            lsum[ri] = lsum[ri] * alpha + rsum;
            mrow[ri] = mnew;
#pragma unroll
            for (int g = 0; g < 8; g++) {
                oacc[g][c0] *= alpha;
                oacc[g][c0 + 1] *= alpha;
            }
        }
        __syncwarp();

        // ---- O += P @ V (2-term; B = Vt single) ----
        const char* vb = smf + FV_BASE + s * 9216;
#pragma unroll
        for (int ks = 0; ks < 4; ks++) {
            const int kc = ks * 32 + lq * 4;
            uint32_t phi[4], plo[4];
            {
                const char* pa = smf + FP_HI + (w * 16 + lr) * 144 + kc;
                phi[0] = *(const uint32_t*)(pa);
                phi[1] = *(const uint32_t*)(pa + 8 * 144);
                phi[2] = *(const uint32_t*)(pa + 16);
                phi[3] = *(const uint32_t*)(pa + 8 * 144 + 16);
                const char* pl = smf + FP_LO + (w * 16 + lr) * 144 + kc;
                plo[0] = *(const uint32_t*)(pl);
                plo[1] = *(const uint32_t*)(pl + 8 * 144);
                plo[2] = *(const uint32_t*)(pl + 16);
                plo[3] = *(const uint32_t*)(pl + 8 * 144 + 16);
            }
            uint32_t b0[8], b1[8];
#pragma unroll
            for (int g = 0; g < 8; g++) {
                const char* pb = vb + (g * 8 + lr) * 144 + kc;
                b0[g] = *(const uint32_t*)(pb);
                b1[g] = *(const uint32_t*)(pb + 16);
            }
#pragma unroll
            for (int g = 0; g < 8; g++) mma_f16(oacc[g], phi, b0[g], b1[g]);
#pragma unroll
            for (int g = 0; g < 8; g++) mma_f16(oacc[g], plo, b0[g], b1[g]);
        }
        __syncthreads();
    }

    // ---- epilogue: AO = O / l -> fp16 hi/lo ----
#pragma unroll
    for (int ri = 0; ri < 2; ri++) {
        float inv = 1.0f / lsum[ri];
        size_t grow = qrow0 + w * 16 + lr + ri * 8;
#pragma unroll
        for (int g = 0; g < 8; g++) {
            int col = h * 64 + g * 8 + lq * 2;
            uint32_t hp, lp;
            split_pack2h(oacc[g][ri * 2] * inv, oacc[g][ri * 2 + 1] * inv, hp, lp);
            *(uint32_t*)(AOhi + grow * DMODEL + col) = hp;
            *(uint32_t*)(AOlo + grow * DMODEL + col) = lp;
        }
    }
}

// ---------------------------------------------------------------------------
extern "C" void kernel_launch(void* const* d_in, const int* in_sizes, int n_in,
                              void* d_out, int out_size)
{
    (void)in_sizes; (void)n_in; (void)out_size;
    const float* x  = (const float*)d_in[0];
    const float* Wq = (const float*)d_in[1];
    const float* Wk = (const float*)d_in[2];
    const float* Wv = (const float*)d_in[3];
    const float* Wo = (const float*)d_in[4];
    const float* bo = (const float*)d_in[5];
    float* out = (float*)d_out;

    __half *Xhi, *Xlo, *W, *Qhi, *Qlo, *Ksp, *Vtp, *AOhi, *AOlo;
    cudaGetSymbolAddress((void**)&Xhi,  g_Xhi);
    cudaGetSymbolAddress((void**)&Xlo,  g_Xlo);
    cudaGetSymbolAddress((void**)&W,    g_W);
    cudaGetSymbolAddress((void**)&Qhi,  g_Qhi);
    cudaGetSymbolAddress((void**)&Qlo,  g_Qlo);
    cudaGetSymbolAddress((void**)&Ksp,  g_Ks);
    cudaGetSymbolAddress((void**)&Vtp,  g_Vt);
    cudaGetSymbolAddress((void**)&AOhi, g_AOhi);
    cudaGetSymbolAddress((void**)&AOlo, g_AOlo);

    convert_split_h<<<512, 256>>>(x, Xhi, Xlo, MM * KK / 4);
    transpose_half4<<<dim3(32, 32, 4), dim3(32, 8)>>>(Wq, Wk, Wv, Wo);

    cudaFuncSetAttribute(gemm_h<0>, cudaFuncAttributeMaxDynamicSharedMemorySize, GEMM_SMEM);
    cudaFuncSetAttribute(gemm_h<1>, cudaFuncAttributeMaxDynamicSharedMemorySize, GEMM_SMEM);
    cudaFuncSetAttribute(gemm_h<2>, cudaFuncAttributeMaxDynamicSharedMemorySize, GEMM_SMEM);
    cudaFuncSetAttribute(gemm_h<3>, cudaFuncAttributeMaxDynamicSharedMemorySize, GEMM_SMEM);
    dim3 gg(NN / 128, MM / 128);
    gemm_h<1><<<gg, 256, GEMM_SMEM>>>(Xhi, Xlo, W + 0 * (size_t)NN * KK,
                                      nullptr, nullptr, Qhi, Qlo, nullptr, 0.125f);
    gemm_h<2><<<gg, 256, GEMM_SMEM>>>(Xhi, Xlo, W + 1 * (size_t)NN * KK,
                                      nullptr, nullptr, nullptr, nullptr, Ksp, 1.0f);
    gemm_h<3><<<gg, 256, GEMM_SMEM>>>(Xhi, Xlo, W + 2 * (size_t)NN * KK,
                                      nullptr, nullptr, nullptr, nullptr, Vtp, 1.0f);

    cudaFuncSetAttribute(flash_h, cudaFuncAttributeMaxDynamicSharedMemorySize, FLASH_SMEM);
    flash_h<<<dim3(SEQ / 64, BATCH * NHEAD), 128, FLASH_SMEM>>>(
        Qhi, Qlo, Ksp, Vtp, AOhi, AOlo);

    gemm_h<0><<<gg, 256, GEMM_SMEM>>>(AOhi, AOlo, W + 3 * (size_t)NN * KK,
                                      out, bo, nullptr, nullptr, nullptr, 1.0f);
}

// round 15
// speedup vs baseline: 1.7829x; 1.2568x over previous
#include <cuda_runtime.h>
#include <cuda_fp16.h>
#include <math.h>
#include <stdint.h>

// Fixed problem shape
#define BATCH 4
#define SEQ   2048
#define DMODEL 1024
#define NHEAD 16
#define HD    64
#define MM (BATCH*SEQ)     // 8192
#define KK DMODEL          // 1024
#define NN DMODEL          // 1024

// fp16 operands (device globals; no allocation allowed)
__device__ __half g_X[MM*KK];          // x single fp16
__device__ __half g_W[4][NN*KK];       // transposed weights [N][K], single fp16
__device__ __half g_Qs[MM*NN];         // Q single fp16, pre-scaled 0.125
__device__ __half g_Ks[MM*NN];         // K single fp16
__device__ __half g_Vt[MM*NN];         // V transposed [(b*16+h)*64+d][key], single
__device__ __half g_AOhi[MM*NN];       // attention out, exact hi/lo pair
__device__ __half g_AOlo[MM*NN];

// ---------------------------------------------------------------------------
__device__ __forceinline__ uint32_t smem_u32(const void* p) {
    uint32_t a;
    asm("{ .reg .u64 t; cvta.to.shared.u64 t, %1; cvt.u32.u64 %0, t; }"
        : "=r"(a) : "l"(p));
    return a;
}
__device__ __forceinline__ void cp_async16(uint32_t dst, const void* src) {
    asm volatile("cp.async.cg.shared.global [%0], [%1], 16;"
                 :: "r"(dst), "l"(src) : "memory");
}
__device__ __forceinline__ void mma_f16(float* d, const uint32_t* a,
                                        uint32_t b0, uint32_t b1) {
    asm volatile(
        "mma.sync.aligned.m16n8k16.row.col.f32.f16.f16.f32 "
        "{%0,%1,%2,%3}, {%4,%5,%6,%7}, {%8,%9}, {%0,%1,%2,%3};"
        : "+f"(d[0]), "+f"(d[1]), "+f"(d[2]), "+f"(d[3])
        : "r"(a[0]), "r"(a[1]), "r"(a[2]), "r"(a[3]), "r"(b0), "r"(b1));
}
__device__ __forceinline__ void split_h(float x, __half& h, __half& l) {
    h = __float2half_rn(x);
    l = __float2half_rn(x - __half2float(h));
}
__device__ __forceinline__ uint16_t h_bits(__half h) { return *(uint16_t*)&h; }
__device__ __forceinline__ uint32_t pack2h(float f0, float f1) {
    __half h0 = __float2half_rn(f0), h1 = __float2half_rn(f1);
    return ((uint32_t)h_bits(h1) << 16) | h_bits(h0);
}
__device__ __forceinline__ void split_pack2h(float f0, float f1,
                                             uint32_t& hp, uint32_t& lp) {
    __half h0, l0, h1, l1;
    split_h(f0, h0, l0);
    split_h(f1, h1, l1);
    hp = ((uint32_t)h_bits(h1) << 16) | h_bits(h0);
    lp = ((uint32_t)h_bits(l1) << 16) | h_bits(l0);
}

// ---------------------------------------------------------------------------
// Convert fp32 -> fp16 single (grid-stride, float4)
// ---------------------------------------------------------------------------
__global__ __launch_bounds__(256) void convert_h(
    const float* __restrict__ src, __half* __restrict__ dst, int n4)
{
    int idx = blockIdx.x * blockDim.x + threadIdx.x;
    int stride = gridDim.x * blockDim.x;
    for (int i = idx; i < n4; i += stride) {
        float4 v = ((const float4*)src)[i];
        __half h[4];
        h[0] = __float2half_rn(v.x);
        h[1] = __float2half_rn(v.y);
        h[2] = __float2half_rn(v.z);
        h[3] = __float2half_rn(v.w);
        ((uint2*)dst)[i] = *(uint2*)h;
    }
}

// ---------------------------------------------------------------------------
// Transpose 4 weights: W[K][N] fp32 -> WT [N][K] single fp16
// ---------------------------------------------------------------------------
__global__ __launch_bounds__(256) void transpose_half4(
    const float* __restrict__ s0, const float* __restrict__ s1,
    const float* __restrict__ s2, const float* __restrict__ s3)
{
    const float* s;
    __half* d;
    switch (blockIdx.z) {
        case 0: s = s0; d = g_W[0]; break;
        case 1: s = s1; d = g_W[1]; break;
        case 2: s = s2; d = g_W[2]; break;
        default: s = s3; d = g_W[3]; break;
    }
    __shared__ float t[32][33];
    int x0 = blockIdx.x * 32, y0 = blockIdx.y * 32;
    int tx = threadIdx.x, ty = threadIdx.y;
#pragma unroll
    for (int j = 0; j < 4; j++)
        t[ty + j * 8][tx] = s[(size_t)(y0 + ty + j * 8) * NN + x0 + tx];
    __syncthreads();
#pragma unroll
    for (int j = 0; j < 4; j++)
        d[(size_t)(x0 + ty + j * 8) * KK + y0 + tx] = __float2half_rn(t[tx][ty + j * 8]);
}

// ---------------------------------------------------------------------------
// fp16 GEMM: C = A[M,K] @ B[N,K]^T. ASPLIT: A is exact hi/lo pair (2 MMAs),
// else single (1 MMA). BK=32, 2-stage cp.async, >=2 CTAs/SM.
// MODE: 0 = fp32 out + bias; 1 = fp16 single out scaled; 2 = fp16 transposed.
// ---------------------------------------------------------------------------
#define BKC 32
#define NCHUNKS (KK / BKC)            // 32
#define ROWB 80
#define ARR_BYTES (128 * ROWB)        // 10240

template <int MODE, bool ASPLIT>
__global__ __launch_bounds__(256, 2) void gemm_h(
    const __half* __restrict__ Ahi, const __half* __restrict__ Alo,
    const __half* __restrict__ B,
    float* __restrict__ C, const float* __restrict__ bias,
    __half* __restrict__ Osng, float scale)
{
    constexpr int NARR = ASPLIT ? 3 : 2;
    constexpr int STAGE_BYTES = NARR * ARR_BYTES;
    extern __shared__ __align__(16) char smb[];
    const uint32_t sbase = smem_u32(smb);
    const int tid = threadIdx.x;
    const int wid = tid >> 5;
    const int l = tid & 31;
    const int wm = wid & 3;
    const int wn = wid >> 2;
    const int m0 = blockIdx.y * 128;
    const int n0 = blockIdx.x * 128;

    float acc[2][8][4];
#pragma unroll
    for (int f = 0; f < 2; f++)
#pragma unroll
        for (int g = 0; g < 8; g++)
#pragma unroll
            for (int r = 0; r < 4; r++) acc[f][g][r] = 0.0f;

    // cp.async chunk c -> stage c&1: NARR arrays x 128 rows x 64B
    auto issue = [&](int c) {
        const int kc0 = c * BKC;
        const uint32_t sb = sbase + (c & 1) * STAGE_BYTES;
#pragma unroll
        for (int i = 0; i < NARR * 2; i++) {
            int id = tid + i * 256;        // 0..NARR*512-1
            int arr = id >> 9;
            int rc = id & 511;
            int row = rc >> 2;
            int ch = rc & 3;
            const __half* gp;
            int grow;
            if (arr == 0)      { gp = Ahi; grow = m0 + row; }
            else if (ASPLIT && arr == 1) { gp = Alo; grow = m0 + row; }
            else               { gp = B;   grow = n0 + row; }
            const void* src = gp + (size_t)grow * KK + kc0 + ch * 8;
            uint32_t dst = sb + arr * ARR_BYTES + row * ROWB + ch * 16;
            cp_async16(dst, src);
        }
    };

    issue(0);
    asm volatile("cp.async.commit_group;" ::: "memory");

    const int lr = l >> 2;
    const int lc = (l & 3) * 2;
    const int boff_arr = (NARR - 1) * ARR_BYTES;   // B array base offset

    for (int c = 0; c < NCHUNKS; c++) {
        if (c + 1 < NCHUNKS) {
            issue(c + 1);
            asm volatile("cp.async.commit_group;" ::: "memory");
            asm volatile("cp.async.wait_group 1;" ::: "memory");
        } else {
            asm volatile("cp.async.wait_group 0;" ::: "memory");
        }
        __syncthreads();

        const char* sb = smb + (c & 1) * STAGE_BYTES;
#pragma unroll
        for (int ks = 0; ks < 2; ks++) {
            const int kc = ks * 16 + lc;
            uint32_t ahi[2][4], alo[2][4];
#pragma unroll
            for (int f = 0; f < 2; f++) {
                int rowA = wm * 32 + f * 16 + lr;
                const char* pa = sb + rowA * ROWB + kc * 2;
                ahi[f][0] = *(const uint32_t*)(pa);
                ahi[f][1] = *(const uint32_t*)(pa + 8 * ROWB);
                ahi[f][2] = *(const uint32_t*)(pa + 16);
                ahi[f][3] = *(const uint32_t*)(pa + 8 * ROWB + 16);
                if (ASPLIT) {
                    const char* pl = pa + ARR_BYTES;
                    alo[f][0] = *(const uint32_t*)(pl);
                    alo[f][1] = *(const uint32_t*)(pl + 8 * ROWB);
                    alo[f][2] = *(const uint32_t*)(pl + 16);
                    alo[f][3] = *(const uint32_t*)(pl + 8 * ROWB + 16);
                }
            }
            uint32_t b0[8], b1[8];
#pragma unroll
            for (int g = 0; g < 8; g++) {
                int rowBn = wn * 64 + g * 8 + lr;
                const char* pb = sb + boff_arr + rowBn * ROWB + kc * 2;
                b0[g] = *(const uint32_t*)(pb);
                b1[g] = *(const uint32_t*)(pb + 16);
            }
#pragma unroll
            for (int g = 0; g < 8; g++)
#pragma unroll
                for (int f = 0; f < 2; f++)
                    mma_f16(acc[f][g], ahi[f], b0[g], b1[g]);
            if (ASPLIT) {
#pragma unroll
                for (int g = 0; g < 8; g++)
#pragma unroll
                    for (int f = 0; f < 2; f++)
                        mma_f16(acc[f][g], alo[f], b0[g], b1[g]);
            }
        }
        __syncthreads();
    }

    // Epilogue
#pragma unroll
    for (int f = 0; f < 2; f++) {
        int r0 = m0 + wm * 32 + f * 16 + lr;
#pragma unroll
        for (int g = 0; g < 8; g++) {
            int cc = n0 + wn * 64 + g * 8 + lc;
            if (MODE == 0) {
                float bx = bias[cc], by = bias[cc + 1];
                float2 v0 = make_float2(acc[f][g][0] + bx, acc[f][g][1] + by);
                float2 v1 = make_float2(acc[f][g][2] + bx, acc[f][g][3] + by);
                *(float2*)(C + (size_t)r0 * NN + cc) = v0;
                *(float2*)(C + (size_t)(r0 + 8) * NN + cc) = v1;
            } else if (MODE == 1) {
                *(uint32_t*)(Osng + (size_t)r0 * NN + cc) =
                    pack2h(acc[f][g][0] * scale, acc[f][g][1] * scale);
                *(uint32_t*)(Osng + (size_t)(r0 + 8) * NN + cc) =
                    pack2h(acc[f][g][2] * scale, acc[f][g][3] * scale);
            } else {
#pragma unroll
                for (int rr = 0; rr < 2; rr++) {
                    int row = r0 + rr * 8;
                    int b = row >> 11, n = row & 2047;
#pragma unroll
                    for (int cj = 0; cj < 2; cj++) {
                        int col = cc + cj;          // = h*64 + d
                        size_t o = ((size_t)(b * 16) * 64 + col) * SEQ + n;
                        Osng[o] = __float2half_rn(acc[f][g][rr * 2 + cj]);
                    }
                }
            }
        }
    }
}

#define GEMM_SMEM_SINGLE (2 * 2 * ARR_BYTES)   // 40960
#define GEMM_SMEM_SPLIT  (2 * 3 * ARR_BYTES)   // 61440

// ---------------------------------------------------------------------------
// Flash attention (causal). Q,K,Vt single fp16 -> QK^T = 1 MMA/product.
// P exact hi/lo pair -> PV = 2 MMAs/product. BM=BN=64, 128 threads.
// smem: Q 0 (9216), K[s] 9216+s*9216, V[s] 27648+s*9216, PH 46080, PL 55296
// ---------------------------------------------------------------------------
#define FK_BASE 9216
#define FV_BASE 27648
#define FP_HI 46080
#define FP_LO 55296
#define FLASH_SMEM 64512

__global__ __launch_bounds__(128, 2) void flash_h(
    const __half* __restrict__ Qs, const __half* __restrict__ Ks,
    const __half* __restrict__ Vt,
    __half* __restrict__ AOhi, __half* __restrict__ AOlo)
{
    extern __shared__ __align__(16) char smf[];
    const uint32_t sb = smem_u32(smf);
    const int tid = threadIdx.x;
    const int w = tid >> 5;
    const int l = tid & 31;
    const int lr = l >> 2;
    const int lq = l & 3;
    const int ib = gridDim.x - 1 - blockIdx.x;
    const int bh = blockIdx.y;
    const int b = bh >> 4;
    const int h = bh & 15;
    const int i0 = ib * 64;
    const size_t qrow0 = (size_t)b * SEQ + i0;

    // ---- load Q (single): 512 16B-chunks ----
#pragma unroll
    for (int i = 0; i < 4; i++) {
        int id = tid + i * 128;
        int row = id >> 3, ch = id & 7;
        cp_async16(sb + row * 144 + ch * 16,
                   Qs + (qrow0 + row) * DMODEL + h * 64 + ch * 8);
    }

    auto issueKV = [&](int jb) {
        const int s = jb & 1;
        const int j0 = jb * 64;
#pragma unroll
        for (int i = 0; i < 8; i++) {
            int id = tid + i * 128;
            int seg = id >> 9;             // 0=K, 1=Vt
            int rc = id & 511;
            int row = rc >> 3, ch = rc & 7;
            const void* src;
            uint32_t dst;
            if (seg == 0) {
                src = Ks + ((size_t)b * SEQ + j0 + row) * DMODEL + h * 64 + ch * 8;
                dst = sb + FK_BASE + s * 9216 + row * 144 + ch * 16;
            } else {
                src = Vt + ((size_t)bh * 64 + row) * SEQ + j0 + ch * 8;
                dst = sb + FV_BASE + s * 9216 + row * 144 + ch * 16;
            }
            cp_async16(dst, src);
        }
    };

    issueKV(0);
    asm volatile("cp.async.commit_group;" ::: "memory");

    float mrow[2] = {-1e30f, -1e30f};
    float lsum[2] = {0.0f, 0.0f};
    float oacc[8][4];
#pragma unroll
    for (int g = 0; g < 8; g++)
#pragma unroll
        for (int r = 0; r < 4; r++) oacc[g][r] = 0.0f;

    for (int jb = 0; jb <= ib; jb++) {
        const int s = jb & 1;
        if (jb < ib) {
            issueKV(jb + 1);
            asm volatile("cp.async.commit_group;" ::: "memory");
            asm volatile("cp.async.wait_group 1;" ::: "memory");
        } else {
            asm volatile("cp.async.wait_group 0;" ::: "memory");
        }
        __syncthreads();

        // ---- S = Q @ K^T (1 MMA per product) ----
        float sacc[8][4];
#pragma unroll
        for (int g = 0; g < 8; g++)
#pragma unroll
            for (int r = 0; r < 4; r++) sacc[g][r] = 0.0f;

        const char* kb = smf + FK_BASE + s * 9216;
#pragma unroll
        for (int ks = 0; ks < 4; ks++) {
            const int kc = ks * 32 + lq * 4;
            uint32_t aq[4];
            {
                const char* pa = smf + (w * 16 + lr) * 144 + kc;
                aq[0] = *(const uint32_t*)(pa);
                aq[1] = *(const uint32_t*)(pa + 8 * 144);
                aq[2] = *(const uint32_t*)(pa + 16);
                aq[3] = *(const uint32_t*)(pa + 8 * 144 + 16);
            }
            uint32_t b0[8], b1[8];
#pragma unroll
            for (int g = 0; g < 8; g++) {
                const char* pb = kb + (g * 8 + lr) * 144 + kc;
                b0[g] = *(const uint32_t*)(pb);
                b1[g] = *(const uint32_t*)(pb + 16);
            }
#pragma unroll
            for (int g = 0; g < 8; g++) mma_f16(sacc[g], aq, b0[g], b1[g]);
        }

        // ---- causal mask on diagonal block ----
        if (jb == ib) {
#pragma unroll
            for (int g = 0; g < 8; g++)
#pragma unroll
                for (int r = 0; r < 4; r++) {
                    int rowL = w * 16 + lr + (r >> 1) * 8;
                    int colL = g * 8 + lq * 2 + (r & 1);
                    if (colL > rowL) sacc[g][r] = -1e30f;
                }
        }

        // ---- online softmax + P split to smem ----
#pragma unroll
        for (int ri = 0; ri < 2; ri++) {
            const int c0 = ri * 2;
            float rmax = -1e30f;
#pragma unroll
            for (int g = 0; g < 8; g++)
                rmax = fmaxf(rmax, fmaxf(sacc[g][c0], sacc[g][c0 + 1]));
            rmax = fmaxf(rmax, __shfl_xor_sync(0xffffffffu, rmax, 1));
            rmax = fmaxf(rmax, __shfl_xor_sync(0xffffffffu, rmax, 2));
            float mnew = fmaxf(mrow[ri], rmax);
            float alpha = __expf(mrow[ri] - mnew);
            float rsum = 0.0f;
            const int prow = w * 16 + lr + ri * 8;
#pragma unroll
            for (int g = 0; g < 8; g++) {
                float p0 = __expf(sacc[g][c0] - mnew);
                float p1 = __expf(sacc[g][c0 + 1] - mnew);
                rsum += p0 + p1;
                uint32_t hp, lp;
                split_pack2h(p0, p1, hp, lp);
                int boff = prow * 144 + (g * 8 + lq * 2) * 2;
                *(uint32_t*)(smf + FP_HI + boff) = hp;
                *(uint32_t*)(smf + FP_LO + boff) = lp;
            }
            rsum += __shfl_xor_sync(0xffffffffu, rsum, 1);
            rsum += __shfl_xor_sync(0xffffffffu, rsum, 2);
            lsum[ri] = lsum[ri] * alpha + rsum;
            mrow[ri] = mnew;
#pragma unroll
            for (int g = 0; g < 8; g++) {
                oacc[g][c0] *= alpha;
                oacc[g][c0 + 1] *= alpha;
            }
        }
        __syncwarp();

        // ---- O += P @ V (P hi/lo, 2 MMAs) ----
        const char* vb = smf + FV_BASE + s * 9216;
#pragma unroll
        for (int ks = 0; ks < 4; ks++) {
            const int kc = ks * 32 + lq * 4;
            uint32_t phi[4], plo[4];
            {
                const char* pa = smf + FP_HI + (w * 16 + lr) * 144 + kc;
                phi[0] = *(const uint32_t*)(pa);
                phi[1] = *(const uint32_t*)(pa + 8 * 144);
                phi[2] = *(const uint32_t*)(pa + 16);
                phi[3] = *(const uint32_t*)(pa + 8 * 144 + 16);
                const char* pl = smf + FP_LO + (w * 16 + lr) * 144 + kc;
                plo[0] = *(const uint32_t*)(pl);
                plo[1] = *(const uint32_t*)(pl + 8 * 144);
                plo[2] = *(const uint32_t*)(pl + 16);
                plo[3] = *(const uint32_t*)(pl + 8 * 144 + 16);
            }
            uint32_t b0[8], b1[8];
#pragma unroll
            for (int g = 0; g < 8; g++) {
                const char* pb = vb + (g * 8 + lr) * 144 + kc;
                b0[g] = *(const uint32_t*)(pb);
                b1[g] = *(const uint32_t*)(pb + 16);
            }
#pragma unroll
            for (int g = 0; g < 8; g++) mma_f16(oacc[g], phi, b0[g], b1[g]);
#pragma unroll
            for (int g = 0; g < 8; g++) mma_f16(oacc[g], plo, b0[g], b1[g]);
        }
        __syncthreads();
    }

    // ---- epilogue: AO = O / l -> fp16 hi/lo ----
#pragma unroll
    for (int ri = 0; ri < 2; ri++) {
        float inv = 1.0f / lsum[ri];
        size_t grow = qrow0 + w * 16 + lr + ri * 8;
#pragma unroll
        for (int g = 0; g < 8; g++) {
            int col = h * 64 + g * 8 + lq * 2;
            uint32_t hp, lp;
            split_pack2h(oacc[g][ri * 2] * inv, oacc[g][ri * 2 + 1] * inv, hp, lp);
            *(uint32_t*)(AOhi + grow * DMODEL + col) = hp;
            *(uint32_t*)(AOlo + grow * DMODEL + col) = lp;
        }
    }
}

// ---------------------------------------------------------------------------
extern "C" void kernel_launch(void* const* d_in, const int* in_sizes, int n_in,
                              void* d_out, int out_size)
{
    (void)in_sizes; (void)n_in; (void)out_size;
    const float* x  = (const float*)d_in[0];
    const float* Wq = (const float*)d_in[1];
    const float* Wk = (const float*)d_in[2];
    const float* Wv = (const float*)d_in[3];
    const float* Wo = (const float*)d_in[4];
    const float* bo = (const float*)d_in[5];
    float* out = (float*)d_out;

    __half *X, *W, *Qs, *Ksp, *Vtp, *AOhi, *AOlo;
    cudaGetSymbolAddress((void**)&X,    g_X);
    cudaGetSymbolAddress((void**)&W,    g_W);
    cudaGetSymbolAddress((void**)&Qs,   g_Qs);
    cudaGetSymbolAddress((void**)&Ksp,  g_Ks);
    cudaGetSymbolAddress((void**)&Vtp,  g_Vt);
    cudaGetSymbolAddress((void**)&AOhi, g_AOhi);
    cudaGetSymbolAddress((void**)&AOlo, g_AOlo);

    convert_h<<<512, 256>>>(x, X, MM * KK / 4);
    transpose_half4<<<dim3(32, 32, 4), dim3(32, 8)>>>(Wq, Wk, Wv, Wo);

    cudaFuncSetAttribute((const void*)gemm_h<1, false>,
                         cudaFuncAttributeMaxDynamicSharedMemorySize, GEMM_SMEM_SINGLE);
    cudaFuncSetAttribute((const void*)gemm_h<2, false>,
                         cudaFuncAttributeMaxDynamicSharedMemorySize, GEMM_SMEM_SINGLE);
    cudaFuncSetAttribute((const void*)gemm_h<0, true>,
                         cudaFuncAttributeMaxDynamicSharedMemorySize, GEMM_SMEM_SPLIT);
    dim3 gg(NN / 128, MM / 128);
    gemm_h<1, false><<<gg, 256, GEMM_SMEM_SINGLE>>>(
        X, nullptr, W + 0 * (size_t)NN * KK, nullptr, nullptr, Qs, 0.125f);
    gemm_h<1, false><<<gg, 256, GEMM_SMEM_SINGLE>>>(
        X, nullptr, W + 1 * (size_t)NN * KK, nullptr, nullptr, Ksp, 1.0f);
    gemm_h<2, false><<<gg, 256, GEMM_SMEM_SINGLE>>>(
        X, nullptr, W + 2 * (size_t)NN * KK, nullptr, nullptr, Vtp, 1.0f);

    cudaFuncSetAttribute(flash_h, cudaFuncAttributeMaxDynamicSharedMemorySize, FLASH_SMEM);
    flash_h<<<dim3(SEQ / 64, BATCH * NHEAD), 128, FLASH_SMEM>>>(
        Qs, Ksp, Vtp, AOhi, AOlo);

    gemm_h<0, true><<<gg, 256, GEMM_SMEM_SPLIT>>>(
        AOhi, AOlo, W + 3 * (size_t)NN * KK, out, bo, nullptr, 1.0f);
}

// round 17
// speedup vs baseline: 1.9652x; 1.1022x over previous
#include <cuda_runtime.h>
#include <cuda_fp16.h>
#include <math.h>
#include <stdint.h>

// Fixed problem shape
#define BATCH 4
#define SEQ   2048
#define DMODEL 1024
#define NHEAD 16
#define HD    64
#define MM (BATCH*SEQ)     // 8192
#define KK DMODEL          // 1024
#define NN DMODEL          // 1024

// fp16 operands (device globals; no allocation allowed)
__device__ __half g_X[MM*KK];          // x single fp16
__device__ __half g_W[4][NN*KK];       // transposed weights [N][K], single fp16
__device__ __half g_Qs[MM*NN];         // Q single fp16, pre-scaled 0.125
__device__ __half g_Ks[MM*NN];         // K single fp16
__device__ __half g_Vt[MM*NN];         // V transposed [(b*16+h)*64+d][key], single
__device__ __half g_AOhi[MM*NN];       // attention out, exact hi/lo pair
__device__ __half g_AOlo[MM*NN];

// ---------------------------------------------------------------------------
__device__ __forceinline__ uint32_t smem_u32(const void* p) {
    uint32_t a;
    asm("{ .reg .u64 t; cvta.to.shared.u64 t, %1; cvt.u32.u64 %0, t; }"
        : "=r"(a) : "l"(p));
    return a;
}
__device__ __forceinline__ void cp_async16(uint32_t dst, const void* src) {
    asm volatile("cp.async.cg.shared.global [%0], [%1], 16;"
                 :: "r"(dst), "l"(src) : "memory");
}
__device__ __forceinline__ void mma_f16(float* d, const uint32_t* a,
                                        uint32_t b0, uint32_t b1) {
    asm volatile(
        "mma.sync.aligned.m16n8k16.row.col.f32.f16.f16.f32 "
        "{%0,%1,%2,%3}, {%4,%5,%6,%7}, {%8,%9}, {%0,%1,%2,%3};"
        : "+f"(d[0]), "+f"(d[1]), "+f"(d[2]), "+f"(d[3])
        : "r"(a[0]), "r"(a[1]), "r"(a[2]), "r"(a[3]), "r"(b0), "r"(b1));
}
__device__ __forceinline__ void ldm_x4(uint32_t& r0, uint32_t& r1,
                                       uint32_t& r2, uint32_t& r3, uint32_t addr) {
    asm volatile("ldmatrix.sync.aligned.m8n8.x4.shared.b16 {%0,%1,%2,%3}, [%4];"
                 : "=r"(r0), "=r"(r1), "=r"(r2), "=r"(r3) : "r"(addr));
}
__device__ __forceinline__ void split_h(float x, __half& h, __half& l) {
    h = __float2half_rn(x);
    l = __float2half_rn(x - __half2float(h));
}
__device__ __forceinline__ uint16_t h_bits(__half h) { return *(uint16_t*)&h; }
__device__ __forceinline__ uint32_t pack2h(float f0, float f1) {
    __half h0 = __float2half_rn(f0), h1 = __float2half_rn(f1);
    return ((uint32_t)h_bits(h1) << 16) | h_bits(h0);
}
__device__ __forceinline__ void split_pack2h(float f0, float f1,
                                             uint32_t& hp, uint32_t& lp) {
    __half h0, l0, h1, l1;
    split_h(f0, h0, l0);
    split_h(f1, h1, l1);
    hp = ((uint32_t)h_bits(h1) << 16) | h_bits(h0);
    lp = ((uint32_t)h_bits(l1) << 16) | h_bits(l0);
}

// ---------------------------------------------------------------------------
// Convert fp32 -> fp16 single (grid-stride, float4)
// ---------------------------------------------------------------------------
__global__ __launch_bounds__(256) void convert_h(
    const float* __restrict__ src, __half* __restrict__ dst, int n4)
{
    int idx = blockIdx.x * blockDim.x + threadIdx.x;
    int stride = gridDim.x * blockDim.x;
    for (int i = idx; i < n4; i += stride) {
        float4 v = ((const float4*)src)[i];
        __half h[4];
        h[0] = __float2half_rn(v.x);
        h[1] = __float2half_rn(v.y);
        h[2] = __float2half_rn(v.z);
        h[3] = __float2half_rn(v.w);
        ((uint2*)dst)[i] = *(uint2*)h;
    }
}

// ---------------------------------------------------------------------------
// Transpose 4 weights: W[K][N] fp32 -> WT [N][K] single fp16
// ---------------------------------------------------------------------------
__global__ __launch_bounds__(256) void transpose_half4(
    const float* __restrict__ s0, const float* __restrict__ s1,
    const float* __restrict__ s2, const float* __restrict__ s3)
{
    const float* s;
    __half* d;
    switch (blockIdx.z) {
        case 0: s = s0; d = g_W[0]; break;
        case 1: s = s1; d = g_W[1]; break;
        case 2: s = s2; d = g_W[2]; break;
        default: s = s3; d = g_W[3]; break;
    }
    __shared__ float t[32][33];
    int x0 = blockIdx.x * 32, y0 = blockIdx.y * 32;
    int tx = threadIdx.x, ty = threadIdx.y;
#pragma unroll
    for (int j = 0; j < 4; j++)
        t[ty + j * 8][tx] = s[(size_t)(y0 + ty + j * 8) * NN + x0 + tx];
    __syncthreads();
#pragma unroll
    for (int j = 0; j < 4; j++)
        d[(size_t)(x0 + ty + j * 8) * KK + y0 + tx] = __float2half_rn(t[tx][ty + j * 8]);
}

// ---------------------------------------------------------------------------
// fp16 GEMM with ldmatrix fragment loads. ASPLIT: A hi/lo (2 MMAs) vs single.
// BK=32, 2-stage cp.async, 2 CTAs/SM. ROWB=80.
// MODE: 0 = fp32 out + bias; 1 = fp16 single out scaled; 2 = fp16 transposed.
// ---------------------------------------------------------------------------
#define BKC 32
#define NCHUNKS (KK / BKC)            // 32
#define ROWB 80
#define ARR_BYTES (128 * ROWB)        // 10240

template <int MODE, bool ASPLIT>
__global__ __launch_bounds__(256, 2) void gemm_h(
    const __half* __restrict__ Ahi, const __half* __restrict__ Alo,
    const __half* __restrict__ B,
    float* __restrict__ C, const float* __restrict__ bias,
    __half* __restrict__ Osng, float scale)
{
    constexpr int NARR = ASPLIT ? 3 : 2;
    constexpr int STAGE_BYTES = NARR * ARR_BYTES;
    extern __shared__ __align__(16) char smb[];
    const uint32_t sbase = smem_u32(smb);
    const int tid = threadIdx.x;
    const int wid = tid >> 5;
    const int l = tid & 31;
    const int wm = wid & 3;
    const int wn = wid >> 2;
    const int m0 = blockIdx.y * 128;
    const int n0 = blockIdx.x * 128;

    float acc[2][8][4];
#pragma unroll
    for (int f = 0; f < 2; f++)
#pragma unroll
        for (int g = 0; g < 8; g++)
#pragma unroll
            for (int r = 0; r < 4; r++) acc[f][g][r] = 0.0f;

    auto issue = [&](int c) {
        const int kc0 = c * BKC;
        const uint32_t sb = sbase + (c & 1) * STAGE_BYTES;
#pragma unroll
        for (int i = 0; i < NARR * 2; i++) {
            int id = tid + i * 256;
            int arr = id >> 9;
            int rc = id & 511;
            int row = rc >> 2;
            int ch = rc & 3;
            const __half* gp;
            int grow;
            if (arr == 0)      { gp = Ahi; grow = m0 + row; }
            else if (ASPLIT && arr == 1) { gp = Alo; grow = m0 + row; }
            else               { gp = B;   grow = n0 + row; }
            const void* src = gp + (size_t)grow * KK + kc0 + ch * 8;
            uint32_t dst = sb + arr * ARR_BYTES + row * ROWB + ch * 16;
            cp_async16(dst, src);
        }
    };

    issue(0);
    asm volatile("cp.async.commit_group;" ::: "memory");

    const int lr = l >> 2;
    const int lc = (l & 3) * 2;
    const int boff_arr = (NARR - 1) * ARR_BYTES;
    // ldmatrix per-thread address components
    const uint32_t a_off = (uint32_t)(((((l >> 3) & 1) * 8) + (l & 7)) * ROWB + (l >> 4) * 16);
    const uint32_t b_row = (uint32_t)((((l >> 4) & 1) * 8 + (l & 7)) * ROWB);
    const uint32_t b_koff = (uint32_t)(((l >> 3) & 1) * 16);

    for (int c = 0; c < NCHUNKS; c++) {
        if (c + 1 < NCHUNKS) {
            issue(c + 1);
            asm volatile("cp.async.commit_group;" ::: "memory");
            asm volatile("cp.async.wait_group 1;" ::: "memory");
        } else {
            asm volatile("cp.async.wait_group 0;" ::: "memory");
        }
        __syncthreads();

        const uint32_t sb = sbase + (c & 1) * STAGE_BYTES;
#pragma unroll
        for (int ks = 0; ks < 2; ks++) {
            const uint32_t kb = ks * 32;
            uint32_t ahi[2][4], alo[2][4];
#pragma unroll
            for (int f = 0; f < 2; f++) {
                uint32_t base = sb + (wm * 32 + f * 16) * ROWB + a_off + kb;
                ldm_x4(ahi[f][0], ahi[f][1], ahi[f][2], ahi[f][3], base);
                if (ASPLIT)
                    ldm_x4(alo[f][0], alo[f][1], alo[f][2], alo[f][3], base + ARR_BYTES);
            }
            uint32_t b0[8], b1[8];
#pragma unroll
            for (int g2 = 0; g2 < 4; g2++) {
                uint32_t addr = sb + boff_arr + (wn * 64 + g2 * 16) * ROWB
                              + b_row + b_koff + kb;
                ldm_x4(b0[2 * g2], b1[2 * g2], b0[2 * g2 + 1], b1[2 * g2 + 1], addr);
            }
#pragma unroll
            for (int g = 0; g < 8; g++)
#pragma unroll
                for (int f = 0; f < 2; f++)
                    mma_f16(acc[f][g], ahi[f], b0[g], b1[g]);
            if (ASPLIT) {
#pragma unroll
                for (int g = 0; g < 8; g++)
#pragma unroll
                    for (int f = 0; f < 2; f++)
                        mma_f16(acc[f][g], alo[f], b0[g], b1[g]);
            }
        }
        __syncthreads();
    }

    // Epilogue
#pragma unroll
    for (int f = 0; f < 2; f++) {
        int r0 = m0 + wm * 32 + f * 16 + lr;
#pragma unroll
        for (int g = 0; g < 8; g++) {
            int cc = n0 + wn * 64 + g * 8 + lc;
            if (MODE == 0) {
                float bx = bias[cc], by = bias[cc + 1];
                float2 v0 = make_float2(acc[f][g][0] + bx, acc[f][g][1] + by);
                float2 v1 = make_float2(acc[f][g][2] + bx, acc[f][g][3] + by);
                *(float2*)(C + (size_t)r0 * NN + cc) = v0;
                *(float2*)(C + (size_t)(r0 + 8) * NN + cc) = v1;
            } else if (MODE == 1) {
                *(uint32_t*)(Osng + (size_t)r0 * NN + cc) =
                    pack2h(acc[f][g][0] * scale, acc[f][g][1] * scale);
                *(uint32_t*)(Osng + (size_t)(r0 + 8) * NN + cc) =
                    pack2h(acc[f][g][2] * scale, acc[f][g][3] * scale);
            } else {
#pragma unroll
                for (int rr = 0; rr < 2; rr++) {
                    int row = r0 + rr * 8;
                    int b = row >> 11, n = row & 2047;
#pragma unroll
                    for (int cj = 0; cj < 2; cj++) {
                        int col = cc + cj;
                        size_t o = ((size_t)(b * 16) * 64 + col) * SEQ + n;
                        Osng[o] = __float2half_rn(acc[f][g][rr * 2 + cj]);
                    }
                }
            }
        }
    }
}

#define GEMM_SMEM_SINGLE (2 * 2 * ARR_BYTES)   // 40960
#define GEMM_SMEM_SPLIT  (2 * 3 * ARR_BYTES)   // 61440

// ---------------------------------------------------------------------------
// Flash attention (causal), ldmatrix fragment loads.
// Q,K,Vt single (QK^T = 1 MMA), P hi/lo (PV = 2 MMAs). BM=BN=64, 128 thr.
// smem: Q 0 (9216), K[s] 9216+s*9216, V[s] 27648+s*9216, PH 46080, PL 55296
// ---------------------------------------------------------------------------
#define FK_BASE 9216
#define FV_BASE 27648
#define FP_HI 46080
#define FP_LO 55296
#define FLASH_SMEM 64512
#define FROW 144

__global__ __launch_bounds__(128, 2) void flash_h(
    const __half* __restrict__ Qs, const __half* __restrict__ Ks,
    const __half* __restrict__ Vt,
    __half* __restrict__ AOhi, __half* __restrict__ AOlo)
{
    extern __shared__ __align__(16) char smf[];
    const uint32_t sb = smem_u32(smf);
    const int tid = threadIdx.x;
    const int w = tid >> 5;
    const int l = tid & 31;
    const int lr = l >> 2;
    const int lq = l & 3;
    const int ib = gridDim.x - 1 - blockIdx.x;
    const int bh = blockIdx.y;
    const int b = bh >> 4;
    const int h = bh & 15;
    const int i0 = ib * 64;
    const size_t qrow0 = (size_t)b * SEQ + i0;

    // ldmatrix per-thread address components (stride FROW)
    const uint32_t a_off = (uint32_t)(((((l >> 3) & 1) * 8) + (l & 7)) * FROW + (l >> 4) * 16);
    const uint32_t b_row = (uint32_t)((((l >> 4) & 1) * 8 + (l & 7)) * FROW);
    const uint32_t b_koff = (uint32_t)(((l >> 3) & 1) * 16);

    // ---- load Q (single): 512 16B-chunks ----
#pragma unroll
    for (int i = 0; i < 4; i++) {
        int id = tid + i * 128;
        int row = id >> 3, ch = id & 7;
        cp_async16(sb + row * FROW + ch * 16,
                   Qs + (qrow0 + row) * DMODEL + h * 64 + ch * 8);
    }

    auto issueKV = [&](int jb) {
        const int s = jb & 1;
        const int j0 = jb * 64;
#pragma unroll
        for (int i = 0; i < 8; i++) {
            int id = tid + i * 128;
            int seg = id >> 9;
            int rc = id & 511;
            int row = rc >> 3, ch = rc & 7;
            const void* src;
            uint32_t dst;
            if (seg == 0) {
                src = Ks + ((size_t)b * SEQ + j0 + row) * DMODEL + h * 64 + ch * 8;
                dst = sb + FK_BASE + s * 9216 + row * FROW + ch * 16;
            } else {
                src = Vt + ((size_t)bh * 64 + row) * SEQ + j0 + ch * 8;
                dst = sb + FV_BASE + s * 9216 + row * FROW + ch * 16;
            }
            cp_async16(dst, src);
        }
    };

    issueKV(0);
    asm volatile("cp.async.commit_group;" ::: "memory");

    float mrow[2] = {-1e30f, -1e30f};
    float lsum[2] = {0.0f, 0.0f};
    float oacc[8][4];
#pragma unroll
    for (int g = 0; g < 8; g++)
#pragma unroll
        for (int r = 0; r < 4; r++) oacc[g][r] = 0.0f;

    for (int jb = 0; jb <= ib; jb++) {
        const int s = jb & 1;
        if (jb < ib) {
            issueKV(jb + 1);
            asm volatile("cp.async.commit_group;" ::: "memory");
            asm volatile("cp.async.wait_group 1;" ::: "memory");
        } else {
            asm volatile("cp.async.wait_group 0;" ::: "memory");
        }
        __syncthreads();

        // ---- S = Q @ K^T (1 MMA per product) ----
        float sacc[8][4];
#pragma unroll
        for (int g = 0; g < 8; g++)
#pragma unroll
            for (int r = 0; r < 4; r++) sacc[g][r] = 0.0f;

        const uint32_t kbse = sb + FK_BASE + s * 9216;
#pragma unroll
        for (int ks = 0; ks < 4; ks++) {
            const uint32_t kb = ks * 32;
            uint32_t aq[4];
            ldm_x4(aq[0], aq[1], aq[2], aq[3], sb + w * 16 * FROW + a_off + kb);
            uint32_t b0[8], b1[8];
#pragma unroll
            for (int g2 = 0; g2 < 4; g2++) {
                uint32_t addr = kbse + g2 * 16 * FROW + b_row + b_koff + kb;
                ldm_x4(b0[2 * g2], b1[2 * g2], b0[2 * g2 + 1], b1[2 * g2 + 1], addr);
            }
#pragma unroll
            for (int g = 0; g < 8; g++) mma_f16(sacc[g], aq, b0[g], b1[g]);
        }

        // ---- causal mask on diagonal block ----
        if (jb == ib) {
#pragma unroll
            for (int g = 0; g < 8; g++)
#pragma unroll
                for (int r = 0; r < 4; r++) {
                    int rowL = w * 16 + lr + (r >> 1) * 8;
                    int colL = g * 8 + lq * 2 + (r & 1);
                    if (colL > rowL) sacc[g][r] = -1e30f;
                }
        }

        // ---- online softmax + P split to smem ----
#pragma unroll
        for (int ri = 0; ri < 2; ri++) {
            const int c0 = ri * 2;
            float rmax = -1e30f;
#pragma unroll
            for (int g = 0; g < 8; g++)
                rmax = fmaxf(rmax, fmaxf(sacc[g][c0], sacc[g][c0 + 1]));
            rmax = fmaxf(rmax, __shfl_xor_sync(0xffffffffu, rmax, 1));
            rmax = fmaxf(rmax, __shfl_xor_sync(0xffffffffu, rmax, 2));
            float mnew = fmaxf(mrow[ri], rmax);
            float alpha = __expf(mrow[ri] - mnew);
            float rsum = 0.0f;
            const int prow = w * 16 + lr + ri * 8;
#pragma unroll
            for (int g = 0; g < 8; g++) {
                float p0 = __expf(sacc[g][c0] - mnew);
                float p1 = __expf(sacc[g][c0 + 1] - mnew);
                rsum += p0 + p1;
                uint32_t hp, lp;
                split_pack2h(p0, p1, hp, lp);
                int boff = prow * FROW + (g * 8 + lq * 2) * 2;
                *(uint32_t*)(smf + FP_HI + boff) = hp;
                *(uint32_t*)(smf + FP_LO + boff) = lp;
            }
            rsum += __shfl_xor_sync(0xffffffffu, rsum, 1);
            rsum += __shfl_xor_sync(0xffffffffu, rsum, 2);
            lsum[ri] = lsum[ri] * alpha + rsum;
            mrow[ri] = mnew;
#pragma unroll
            for (int g = 0; g < 8; g++) {
                oacc[g][c0] *= alpha;
                oacc[g][c0 + 1] *= alpha;
            }
        }
        __syncwarp();

        // ---- O += P @ V (P hi/lo, 2 MMAs) ----
        const uint32_t vbse = sb + FV_BASE + s * 9216;
#pragma unroll
        for (int ks = 0; ks < 4; ks++) {
            const uint32_t kb = ks * 32;
            uint32_t phi[4], plo[4];
            ldm_x4(phi[0], phi[1], phi[2], phi[3],
                   sb + FP_HI + w * 16 * FROW + a_off + kb);
            ldm_x4(plo[0], plo[1], plo[2], plo[3],
                   sb + FP_LO + w * 16 * FROW + a_off + kb);
            uint32_t b0[8], b1[8];
#pragma unroll
            for (int g2 = 0; g2 < 4; g2++) {
                uint32_t addr = vbse + g2 * 16 * FROW + b_row + b_koff + kb;
                ldm_x4(b0[2 * g2], b1[2 * g2], b0[2 * g2 + 1], b1[2 * g2 + 1], addr);
            }
#pragma unroll
            for (int g = 0; g < 8; g++) mma_f16(oacc[g], phi, b0[g], b1[g]);
#pragma unroll
            for (int g = 0; g < 8; g++) mma_f16(oacc[g], plo, b0[g], b1[g]);
        }
        __syncthreads();
    }

    // ---- epilogue: AO = O / l -> fp16 hi/lo ----
#pragma unroll
    for (int ri = 0; ri < 2; ri++) {
        float inv = 1.0f / lsum[ri];
        size_t grow = qrow0 + w * 16 + lr + ri * 8;
#pragma unroll
        for (int g = 0; g < 8; g++) {
            int col = h * 64 + g * 8 + lq * 2;
            uint32_t hp, lp;
            split_pack2h(oacc[g][ri * 2] * inv, oacc[g][ri * 2 + 1] * inv, hp, lp);
            *(uint32_t*)(AOhi + grow * DMODEL + col) = hp;
            *(uint32_t*)(AOlo + grow * DMODEL + col) = lp;
        }
    }
}

// ---------------------------------------------------------------------------
extern "C" void kernel_launch(void* const* d_in, const int* in_sizes, int n_in,
                              void* d_out, int out_size)
{
    (void)in_sizes; (void)n_in; (void)out_size;
    const float* x  = (const float*)d_in[0];
    const float* Wq = (const float*)d_in[1];
    const float* Wk = (const float*)d_in[2];
    const float* Wv = (const float*)d_in[3];
    const float* Wo = (const float*)d_in[4];
    const float* bo = (const float*)d_in[5];
    float* out = (float*)d_out;

    __half *X, *W, *Qs, *Ksp, *Vtp, *AOhi, *AOlo;
    cudaGetSymbolAddress((void**)&X,    g_X);
    cudaGetSymbolAddress((void**)&W,    g_W);
    cudaGetSymbolAddress((void**)&Qs,   g_Qs);
    cudaGetSymbolAddress((void**)&Ksp,  g_Ks);
    cudaGetSymbolAddress((void**)&Vtp,  g_Vt);
    cudaGetSymbolAddress((void**)&AOhi, g_AOhi);
    cudaGetSymbolAddress((void**)&AOlo, g_AOlo);

    convert_h<<<512, 256>>>(x, X, MM * KK / 4);
    transpose_half4<<<dim3(32, 32, 4), dim3(32, 8)>>>(Wq, Wk, Wv, Wo);

    cudaFuncSetAttribute((const void*)gemm_h<1, false>,
                         cudaFuncAttributeMaxDynamicSharedMemorySize, GEMM_SMEM_SINGLE);
    cudaFuncSetAttribute((const void*)gemm_h<2, false>,
                         cudaFuncAttributeMaxDynamicSharedMemorySize, GEMM_SMEM_SINGLE);
    cudaFuncSetAttribute((const void*)gemm_h<0, true>,
                         cudaFuncAttributeMaxDynamicSharedMemorySize, GEMM_SMEM_SPLIT);
    dim3 gg(NN / 128, MM / 128);
    gemm_h<1, false><<<gg, 256, GEMM_SMEM_SINGLE>>>(
        X, nullptr, W + 0 * (size_t)NN * KK, nullptr, nullptr, Qs, 0.125f);
    gemm_h<1, false><<<gg, 256, GEMM_SMEM_SINGLE>>>(
        X, nullptr, W + 1 * (size_t)NN * KK, nullptr, nullptr, Ksp, 1.0f);
    gemm_h<2, false><<<gg, 256, GEMM_SMEM_SINGLE>>>(
        X, nullptr, W + 2 * (size_t)NN * KK, nullptr, nullptr, Vtp, 1.0f);

    cudaFuncSetAttribute(flash_h, cudaFuncAttributeMaxDynamicSharedMemorySize, FLASH_SMEM);
    flash_h<<<dim3(SEQ / 64, BATCH * NHEAD), 128, FLASH_SMEM>>>(
        Qs, Ksp, Vtp, AOhi, AOlo);

    gemm_h<0, true><<<gg, 256, GEMM_SMEM_SPLIT>>>(
        AOhi, AOlo, W + 3 * (size_t)NN * KK, out, bo, nullptr, 1.0f);
}